// round 14
// baseline (speedup 1.0000x reference)
#include <cuda_runtime.h>
#include <math.h>

#define BATCH 64
#define CIN 32
#define T_IN 2048
#define FIL 64
#define WIN 5
#define T1 2044
#define T2 2040
#define LL 2036
#define DA 64
#define DD 256
#define SEC 11
#define BN_EPSF 1e-5f

#define TILE 128        // pooled outputs per k1 block
#define INT_ 136        // input positions per k1 tile
#define NTILE1 16       // k1 tiles over T2
#define TILE3 128       // l positions per k3 block
#define NTILE3 16       // k3 tiles over LL
#define SH3 68          // float4-alignable [t][f] stride in k3
#define JP 68           // padded a-stride for sGT in k5

// ---------------- scratch (device globals) ----------------
__device__ float g_h2[BATCH * T2 * FIL];            // pooled conv1 out, [b][t][f]
__device__ float g_part[NTILE1 * BATCH * FIL * 2];  // per-block BN partials
__device__ float g_we2[FIL * WIN];
__device__ float g_cterm;
__device__ int   g_idx[BATCH * LL];
__device__ float g_W1T[LL * DA];                    // W1 transposed [l][a]
__device__ float g_w1T[CIN * WIN * FIL];            // conv1 w transposed [c][k][f]
__device__ float g_Gc[BATCH * DD * DA];             // compact G [b][jj][a]
__device__ int   g_jlist[BATCH * DD];
__device__ int   g_nact[BATCH];
__device__ int   g_cnt[BATCH * DD];
__device__ float g_A[BATCH * DD];

// ---------------- K0: transposes ----------------
extern "C" __global__ void k0_prep(const float* __restrict__ W1,
                                   const float* __restrict__ w1) {
    int t = blockIdx.x * 256 + threadIdx.x;
    if (t < LL * DA) {
        int l = t >> 6, a = t & 63;
        g_W1T[t] = W1[a * LL + l];
    }
    int u = t - LL * DA;
    if (u >= 0 && u < CIN * WIN * FIL) {
        int f = u & 63, ck = u >> 6;          // ck = c*5+k
        g_w1T[u] = w1[f * (CIN * WIN) + ck];
    }
}

// ---------------- K1: conv1 + maxpool5 + BN partials (R11, validated) --------
extern "C" __global__ void __launch_bounds__(256, 3)
k1_conv_pool(const float* __restrict__ x, const float* __restrict__ b1) {
    extern __shared__ float sm[];
    float* sx  = sm;                    // CIN*INT_  (4352)
    float* sst = sx + CIN * INT_;       // 8*32*2    (512)

    int tile = blockIdx.x, b = blockIdx.y;
    int t0 = tile * TILE;
    int tid = threadIdx.x;
    int w = tid >> 5, lane = tid & 31;
    int q = w >> 1, fhi = w & 1;
    int f = fhi * 32 + lane;
    int npool = min(TILE, T2 - t0);

    for (int i = tid; i < CIN * INT_; i += 256) {
        int c = i / INT_, p = i - c * INT_;
        int g = t0 + p;
        sx[i] = (g < T_IN) ? x[(b * CIN + c) * T_IN + g] : 0.f;
    }
    __syncthreads();

    float acc[36];
    float bias = __ldg(&b1[f]);
#pragma unroll
    for (int i = 0; i < 36; ++i) acc[i] = bias;

    int base = q * 32;
    for (int c = 0; c < CIN; ++c) {
        const float* wr = g_w1T + c * WIN * FIL + f;
        float w0 = __ldg(wr), wa = __ldg(wr + FIL), wb = __ldg(wr + 2 * FIL),
              wc = __ldg(wr + 3 * FIL), wd = __ldg(wr + 4 * FIL);
        const float* xr = sx + c * INT_ + base;
        float x0 = xr[0], x1 = xr[1], x2 = xr[2], x3 = xr[3];
#pragma unroll
        for (int i = 0; i < 36; ++i) {
            float x4 = xr[i + 4];
            acc[i] += w0 * x0 + wa * x1 + wb * x2 + wc * x3 + wd * x4;
            x0 = x1; x1 = x2; x2 = x3; x3 = x4;
        }
    }

    float ls = 0.f, ls2 = 0.f;
    float* h2row = g_h2 + ((size_t)b * T2 + t0) * FIL + f;
#pragma unroll
    for (int i = 0; i < 32; ++i) {
        float m = acc[i];
        m = fmaxf(m, acc[i + 1]); m = fmaxf(m, acc[i + 2]);
        m = fmaxf(m, acc[i + 3]); m = fmaxf(m, acc[i + 4]);
        int p = base + i;
        if (p < npool) {
            h2row[(size_t)p * FIL] = m;
            ls += m; ls2 += m * m;
        }
    }
    sst[(w * 32 + lane) * 2 + 0] = ls;
    sst[(w * 32 + lane) * 2 + 1] = ls2;
    __syncthreads();

    if (tid < FIL) {
        int fh = tid >> 5, ln = tid & 31;
        float s = 0.f, s2 = 0.f;
        for (int qq = 0; qq < 4; ++qq) {
            int ww = qq * 2 + fh;
            s  += sst[(ww * 32 + ln) * 2 + 0];
            s2 += sst[(ww * 32 + ln) * 2 + 1];
        }
        int blk = b * NTILE1 + tile;
        g_part[(blk * FIL + tid) * 2 + 0] = s;
        g_part[(blk * FIL + tid) * 2 + 1] = s2;
    }
}

// ---------------- K2: reduce BN stats (UNCHANGED / validated) ----------------
extern "C" __global__ void k2_stats(const float* __restrict__ w2,
                                    const float* __restrict__ b2,
                                    const float* __restrict__ gamma,
                                    const float* __restrict__ beta) {
    __shared__ double ssum[256], ssum2[256];
    __shared__ float sct[FIL];
    int tid = threadIdx.x;  // 256
    int f = tid & 63, seg = tid >> 6;
    double s = 0.0, s2 = 0.0;
    for (int blk = seg; blk < NTILE1 * BATCH; blk += 4) {
        s  += (double)g_part[(blk * FIL + f) * 2 + 0];
        s2 += (double)g_part[(blk * FIL + f) * 2 + 1];
    }
    ssum[tid] = s; ssum2[tid] = s2;
    __syncthreads();
    if (seg == 0) {
        for (int k = 1; k < 4; ++k) { s += ssum[f + 64 * k]; s2 += ssum2[f + 64 * k]; }
        double N = (double)BATCH * (double)T2;
        double mud = s / N;
        float mu = (float)mud;
        float var = (float)(s2 / N - mud * mud);
        float scale = gamma[f] * rsqrtf(var + BN_EPSF);
        float shift = beta[f] - mu * scale;
        float wsum = 0.f;
        for (int k = 0; k < WIN; ++k) {
            float wv = w2[f * WIN + k];
            g_we2[f * WIN + k] = wv * scale;
            wsum += wv;
        }
        sct[f] = shift * wsum;
    }
    __syncthreads();
    if (tid == 0) {
        float c = b2[0];
        for (int i = 0; i < FIL; ++i) c += sct[i];
        g_cterm = c;
    }
}

// ---------------- K3: conv2 + relu + sigmoid + bucket index (R11 form) -------
extern "C" __global__ void k3_conv2_idx() {
    extern __shared__ float sm3[];
    float* sh   = sm3;                      // (TILE3+4)*SH3
    float* swe2 = sh + (TILE3 + 4) * SH3;   // WIN*FIL  layout [k][f]
    __shared__ float sct;
    int tile = blockIdx.x, b = blockIdx.y;
    int t0 = tile * TILE3;
    int tid = threadIdx.x;  // 128

    for (int o = tid; o < (TILE3 + 4) * FIL; o += 128) {
        int tl = o >> 6, ff = o & 63;
        int t = t0 + tl;
        sh[tl * SH3 + ff] = (t < T2) ? g_h2[((size_t)b * T2 + t) * FIL + ff] : 0.f;
    }
    for (int o = tid; o < FIL * WIN; o += 128) {
        int ff = o & 63, k = o >> 6;     // o = k*64+ff
        swe2[k * FIL + ff] = g_we2[ff * WIN + k];
    }
    if (tid == 0) sct = g_cterm;
    __syncthreads();

    int l = t0 + tid;
    if (l < LL) {
        float z = sct;
        const float* hb = sh + tid * SH3;
#pragma unroll 4
        for (int f = 0; f < FIL; f += 4) {
            float4 h0 = *(const float4*)(hb + f);
            float4 h1 = *(const float4*)(hb + SH3 + f);
            float4 h2 = *(const float4*)(hb + 2 * SH3 + f);
            float4 h3 = *(const float4*)(hb + 3 * SH3 + f);
            float4 h4 = *(const float4*)(hb + 4 * SH3 + f);
            float4 w0 = *(const float4*)(swe2 + f);
            float4 w1 = *(const float4*)(swe2 + FIL + f);
            float4 w2 = *(const float4*)(swe2 + 2 * FIL + f);
            float4 w3 = *(const float4*)(swe2 + 3 * FIL + f);
            float4 w4 = *(const float4*)(swe2 + 4 * FIL + f);
            z += w0.x * h0.x + w1.x * h1.x + w2.x * h2.x + w3.x * h3.x + w4.x * h4.x;
            z += w0.y * h0.y + w1.y * h1.y + w2.y * h2.y + w3.y * h3.y + w4.y * h4.y;
            z += w0.z * h0.z + w1.z * h1.z + w2.z * h2.z + w3.z * h3.z + w4.z * h4.z;
            z += w0.w * h0.w + w1.w * h1.w + w2.w * h2.w + w3.w * h3.w + w4.w * h4.w;
        }
        z = fmaxf(z, 0.f);
        float c = 1.f / (1.f + expf(-z));
        int iv = (int)ceilf(c * 256.f) - 1;
        iv = max(0, min(255, iv));
        g_idx[b * LL + l] = iv;
    }
}

// ---------------- K4: ATOMIC-FREE mod-4 ownership scatter --------------------
// 256 threads = (a in 0..63) x (r = tid>>6 in 0..3). ALL threads walk the full
// l-sequence with run-length register accumulation; thread (a,r) FLUSHES only
// buckets with j%4==r. Each (a,j) cell has exactly one owner -> plain
// LDS+FADD+STS, zero ATOMS (the 64-cyc/warp-flush ATOMS wall is gone).
// All branches warp-uniform (shared j stream; r uniform per warp). Flush
// addresses (a*257+j): banks (a+j)%32 -> conflict-free. Sum order differs from
// R7 only in grouping — proven tolerated (R7/R10 both passed).
extern "C" __global__ void k4_scatter() {
    extern __shared__ float sm4[];
    float* sG   = sm4;                         // DA*257
    int* sidx   = (int*)(sG + DA * 257);       // 2048 (2036 used)
    int* shist  = sidx + 2048;                 // 256
    int* sscan  = shist + 256;                 // 256
    int* spos   = sscan + 256;                 // 256
    int b = blockIdx.x;
    int tid = threadIdx.x;  // 256
    int a = tid & 63, r = tid >> 6;

    for (int o = tid; o < DA * 257; o += 256) sG[o] = 0.f;
    for (int o = tid; o < LL; o += 256) sidx[o] = g_idx[b * LL + o];
    shist[tid] = 0;
    __syncthreads();

    {
        float* row = sG + a * 257;
        const float* w1a = g_W1T + a;
        int jprev = -1, cacc = 0;
        float wacc = 0.f;
#pragma unroll 4
        for (int l = 0; l < LL; ++l) {
            int j = sidx[l];                    // broadcast LDS (warp-uniform)
            float wv = __ldg(w1a + l * DA);     // coalesced across a
            if (j != jprev) {                   // warp-uniform branch
                if (jprev >= 0 && (jprev & 3) == r) {
                    row[jprev] += wacc;         // exclusive owner: no atomic
                    if (a == 0) shist[jprev] += cacc;
                }
                jprev = j; wacc = wv; cacc = 1;
            } else { wacc += wv; ++cacc; }
        }
        if (jprev >= 0 && (jprev & 3) == r) {
            row[jprev] += wacc;
            if (a == 0) shist[jprev] += cacc;
        }
    }
    __syncthreads();

    // compact: prefix-sum of occupancy flags (identical to validated R7)
    int cflag = (shist[tid] > 0) ? 1 : 0;
    sscan[tid] = cflag;
    __syncthreads();
    for (int off = 1; off < 256; off <<= 1) {
        int add = (tid >= off) ? sscan[tid - off] : 0;
        __syncthreads();
        sscan[tid] += add;
        __syncthreads();
    }
    int pos = sscan[tid] - cflag;
    spos[tid] = pos;
    if (cflag) g_jlist[b * DD + pos] = tid;
    if (tid == 255) g_nact[b] = sscan[255];
    g_cnt[b * DD + tid] = shist[tid];
    __syncthreads();

    for (int o = tid; o < DD * DA; o += 256) {
        int j = o >> 6, aa = o & 63;
        if (shist[j] > 0)
            g_Gc[((size_t)b * DD + spos[j]) * DA + aa] = sG[aa * 257 + j];
    }
}

// ---------------- K5: t = tanh(Gc @ emb_active); A = W2^T t ----------------
extern "C" __global__ void k5_gemm(const float* __restrict__ emb,
                                   const float* __restrict__ W2) {
    extern __shared__ float sm5[];
    float* sGT = sm5;                   // DD*JP (only nact rows used)
    float* sA  = sGT + DD * JP;         // 128
    float* sW2 = sA + 128;              // 64
    int*   sjl = (int*)(sW2 + DA);      // 256
    int b = blockIdx.x, half = blockIdx.y;
    int tid = threadIdx.x;  // 128

    int nact = g_nact[b];
    for (int o = tid; o < nact * DA; o += 128) {
        int jj = o >> 6, a = o & 63;
        sGT[jj * JP + a] = g_Gc[((size_t)b * DD + jj) * DA + a];
    }
    for (int o = tid; o < DD; o += 128) sjl[o] = g_jlist[b * DD + o];
    sA[tid] = 0.f;
    if (tid < DA) sW2[tid] = W2[tid];
    __syncthreads();

    int ta = tid >> 4, td = tid & 15;   // 8 x 16
    int a0 = ta * 8;
    int d0 = half * 128 + td * 8;
    float acc[8][8];
#pragma unroll
    for (int r = 0; r < 8; ++r)
#pragma unroll
        for (int s = 0; s < 8; ++s) acc[r][s] = 0.f;

    for (int jj = 0; jj < nact; ++jj) {
        const float* er = emb + (size_t)sjl[jj] * DD + d0;
        float4 ga = *(const float4*)&sGT[jj * JP + a0];
        float4 gb = *(const float4*)&sGT[jj * JP + a0 + 4];
        float4 e0 = __ldg((const float4*)er);
        float4 e1 = __ldg((const float4*)(er + 4));
        float gv[8] = {ga.x, ga.y, ga.z, ga.w, gb.x, gb.y, gb.z, gb.w};
        float ev[8] = {e0.x, e0.y, e0.z, e0.w, e1.x, e1.y, e1.z, e1.w};
#pragma unroll
        for (int r = 0; r < 8; ++r)
#pragma unroll
            for (int s = 0; s < 8; ++s)
                acc[r][s] = fmaf(gv[r], ev[s], acc[r][s]);
    }

    float pA[8];
#pragma unroll
    for (int s = 0; s < 8; ++s) pA[s] = 0.f;
#pragma unroll
    for (int r = 0; r < 8; ++r) {
        float wv = sW2[a0 + r];
#pragma unroll
        for (int s = 0; s < 8; ++s)
            pA[s] = fmaf(wv, tanhf(acc[r][s]), pA[s]);
    }
#pragma unroll
    for (int s = 0; s < 8; ++s)
        atomicAdd(&sA[td * 8 + s], pA[s]);
    __syncthreads();
    g_A[b * DD + half * 128 + tid] = sA[tid];
}

// ---------------- K6: bucket softmax + att gather + scores ----------------
extern "C" __global__ void k6_final(const float* __restrict__ emb,
                                    const float* __restrict__ lin_w,
                                    const float* __restrict__ lin_b,
                                    float* __restrict__ out) {
    __shared__ float sA[DD];
    __shared__ float sE[DD];
    __shared__ float red[256];
    int b = blockIdx.x;
    int tid = threadIdx.x;  // 256
    sA[tid] = g_A[b * DD + tid];
    __syncthreads();

    int j = tid;
    float P = 0.f;
    const float4* er = (const float4*)(emb + (size_t)j * DD);
#pragma unroll 8
    for (int d4 = 0; d4 < DD / 4; ++d4) {
        float4 e = __ldg(er + d4);
        P += e.x * sA[d4 * 4 + 0] + e.y * sA[d4 * 4 + 1]
           + e.z * sA[d4 * 4 + 2] + e.w * sA[d4 * 4 + 3];
    }
    int cj = g_cnt[b * DD + j];
    red[tid] = (cj > 0) ? P : -3.0e38f;
    __syncthreads();
    for (int st = 128; st > 0; st >>= 1) {
        if (tid < st) red[tid] = fmaxf(red[tid], red[tid + st]);
        __syncthreads();
    }
    float m = red[0];
    __syncthreads();
    float ex = (cj > 0) ? expf(P - m) : 0.f;
    red[tid] = (float)cj * ex;
    __syncthreads();
    for (int st = 128; st > 0; st >>= 1) {
        if (tid < st) red[tid] += red[tid + st];
        __syncthreads();
    }
    float Z = red[0];
    sE[j] = ex / Z;
    __syncthreads();

    for (int l = tid; l < LL; l += 256)
        out[b * LL + l] = sE[g_idx[b * LL + l]];

    if (tid < SEC) {
        float s = lin_b[tid];
        const float* wr = lin_w + tid * DD;
        for (int d = 0; d < DD; ++d) s += wr[d] * sA[d];
        out[BATCH * LL + b * SEC + tid] = s;
    }
}

// ---------------- launch ----------------
extern "C" void kernel_launch(void* const* d_in, const int* in_sizes, int n_in,
                              void* d_out, int out_size) {
    const float* x     = (const float*)d_in[0];
    const float* c1w   = (const float*)d_in[1];
    const float* c1b   = (const float*)d_in[2];
    const float* gamma = (const float*)d_in[3];
    const float* beta  = (const float*)d_in[4];
    const float* c2w   = (const float*)d_in[5];
    const float* c2b   = (const float*)d_in[6];
    const float* emb   = (const float*)d_in[7];
    const float* W1    = (const float*)d_in[8];
    const float* W2    = (const float*)d_in[9];
    const float* lw    = (const float*)d_in[10];
    const float* lb    = (const float*)d_in[11];
    float* out = (float*)d_out;

    size_t sm1 = (size_t)(CIN * INT_ + 8 * 32 * 2) * sizeof(float);
    size_t sm3 = (size_t)((TILE3 + 4) * SH3 + WIN * FIL) * sizeof(float);
    size_t sm4 = (size_t)DA * 257 * sizeof(float) + (2048 + 3 * 256) * sizeof(int);
    size_t sm5 = (size_t)(DD * JP + 128 + DA) * sizeof(float) + DD * sizeof(int);
    cudaFuncSetAttribute(k1_conv_pool, cudaFuncAttributeMaxDynamicSharedMemorySize, (int)sm1);
    cudaFuncSetAttribute(k3_conv2_idx, cudaFuncAttributeMaxDynamicSharedMemorySize, (int)sm3);
    cudaFuncSetAttribute(k4_scatter,   cudaFuncAttributeMaxDynamicSharedMemorySize, (int)sm4);
    cudaFuncSetAttribute(k5_gemm,      cudaFuncAttributeMaxDynamicSharedMemorySize, (int)sm5);

    int n0 = LL * DA + CIN * WIN * FIL;
    k0_prep<<<(n0 + 255) / 256, 256>>>(W1, c1w);
    k1_conv_pool<<<dim3(NTILE1, BATCH), 256, sm1>>>(x, c1b);
    k2_stats<<<1, 256>>>(c2w, c2b, gamma, beta);
    k3_conv2_idx<<<dim3(NTILE3, BATCH), 128, sm3>>>();
    k4_scatter<<<BATCH, 256, sm4>>>();
    k5_gemm<<<dim3(BATCH, 2), 128, sm5>>>(emb, W2);
    k6_final<<<BATCH, 256>>>(emb, lw, lb, out);
}

// round 15
// speedup vs baseline: 1.7702x; 1.7702x over previous
#include <cuda_runtime.h>
#include <math.h>

#define BATCH 64
#define CIN 32
#define T_IN 2048
#define FIL 64
#define WIN 5
#define T1 2044
#define T2 2040
#define LL 2036
#define DA 64
#define DD 256
#define SEC 11
#define BN_EPSF 1e-5f

#define TILE 128        // pooled outputs per k1 block
#define INT_ 136        // input positions per k1 tile
#define NTILE1 16       // k1 tiles over T2
#define TILE3 128       // l positions per k3 block
#define NTILE3 16       // k3 tiles over LL
#define SH3 68          // float4-alignable [t][f] stride in k3
#define JP 68           // padded a-stride for sGT in k5

// ---------------- scratch (device globals) ----------------
__device__ float g_h2[BATCH * T2 * FIL];            // pooled conv1 out, [b][t][f]
__device__ float g_part[NTILE1 * BATCH * FIL * 2];  // per-block BN partials
__device__ float g_we2[FIL * WIN];
__device__ float g_cterm;
__device__ int   g_idx[BATCH * LL];
__device__ float g_W1T[LL * DA];                    // W1 transposed [l][a]
__device__ float g_w1T[CIN * WIN * FIL];            // conv1 w transposed [c][k][f]
__device__ float g_Gc[BATCH * DD * DA];             // compact G [b][jj][a]
__device__ int   g_jlist[BATCH * DD];
__device__ int   g_nact[BATCH];
__device__ int   g_cnt[BATCH * DD];
__device__ float g_A[BATCH * DD];

// ---------------- K0 split into 3 launches so k1 is the 4th launch ----------
// (ncu has captured the 4th launch every round; this steers it onto k1.)
extern "C" __global__ void k0a_prep(const float* __restrict__ W1) {
    int t = blockIdx.x * 256 + threadIdx.x;          // first half of W1T
    if (t < (LL * DA) / 2) {
        int l = t >> 6, a = t & 63;
        g_W1T[t] = W1[a * LL + l];
    }
}
extern "C" __global__ void k0b_prep(const float* __restrict__ W1) {
    int t = (LL * DA) / 2 + blockIdx.x * 256 + threadIdx.x;  // second half
    if (t < LL * DA) {
        int l = t >> 6, a = t & 63;
        g_W1T[t] = W1[a * LL + l];
    }
}
extern "C" __global__ void k0c_prep(const float* __restrict__ w1) {
    int u = blockIdx.x * 256 + threadIdx.x;
    if (u < CIN * WIN * FIL) {
        int f = u & 63, ck = u >> 6;          // ck = c*5+k
        g_w1T[u] = w1[f * (CIN * WIN) + ck];
    }
}

// ---------------- K1: conv1 + maxpool5 + BN partials (R11, validated) --------
extern "C" __global__ void __launch_bounds__(256, 3)
k1_conv_pool(const float* __restrict__ x, const float* __restrict__ b1) {
    extern __shared__ float sm[];
    float* sx  = sm;                    // CIN*INT_  (4352)
    float* sst = sx + CIN * INT_;       // 8*32*2    (512)

    int tile = blockIdx.x, b = blockIdx.y;
    int t0 = tile * TILE;
    int tid = threadIdx.x;
    int w = tid >> 5, lane = tid & 31;
    int q = w >> 1, fhi = w & 1;
    int f = fhi * 32 + lane;
    int npool = min(TILE, T2 - t0);

    for (int i = tid; i < CIN * INT_; i += 256) {
        int c = i / INT_, p = i - c * INT_;
        int g = t0 + p;
        sx[i] = (g < T_IN) ? x[(b * CIN + c) * T_IN + g] : 0.f;
    }
    __syncthreads();

    float acc[36];
    float bias = __ldg(&b1[f]);
#pragma unroll
    for (int i = 0; i < 36; ++i) acc[i] = bias;

    int base = q * 32;
    for (int c = 0; c < CIN; ++c) {
        const float* wr = g_w1T + c * WIN * FIL + f;
        float w0 = __ldg(wr), wa = __ldg(wr + FIL), wb = __ldg(wr + 2 * FIL),
              wc = __ldg(wr + 3 * FIL), wd = __ldg(wr + 4 * FIL);
        const float* xr = sx + c * INT_ + base;
        float x0 = xr[0], x1 = xr[1], x2 = xr[2], x3 = xr[3];
#pragma unroll
        for (int i = 0; i < 36; ++i) {
            float x4 = xr[i + 4];
            acc[i] += w0 * x0 + wa * x1 + wb * x2 + wc * x3 + wd * x4;
            x0 = x1; x1 = x2; x2 = x3; x3 = x4;
        }
    }

    float ls = 0.f, ls2 = 0.f;
    float* h2row = g_h2 + ((size_t)b * T2 + t0) * FIL + f;
#pragma unroll
    for (int i = 0; i < 32; ++i) {
        float m = acc[i];
        m = fmaxf(m, acc[i + 1]); m = fmaxf(m, acc[i + 2]);
        m = fmaxf(m, acc[i + 3]); m = fmaxf(m, acc[i + 4]);
        int p = base + i;
        if (p < npool) {
            h2row[(size_t)p * FIL] = m;
            ls += m; ls2 += m * m;
        }
    }
    sst[(w * 32 + lane) * 2 + 0] = ls;
    sst[(w * 32 + lane) * 2 + 1] = ls2;
    __syncthreads();

    if (tid < FIL) {
        int fh = tid >> 5, ln = tid & 31;
        float s = 0.f, s2 = 0.f;
        for (int qq = 0; qq < 4; ++qq) {
            int ww = qq * 2 + fh;
            s  += sst[(ww * 32 + ln) * 2 + 0];
            s2 += sst[(ww * 32 + ln) * 2 + 1];
        }
        int blk = b * NTILE1 + tile;
        g_part[(blk * FIL + tid) * 2 + 0] = s;
        g_part[(blk * FIL + tid) * 2 + 1] = s2;
    }
}

// ---------------- K2: reduce BN stats (UNCHANGED / validated) ----------------
extern "C" __global__ void k2_stats(const float* __restrict__ w2,
                                    const float* __restrict__ b2,
                                    const float* __restrict__ gamma,
                                    const float* __restrict__ beta) {
    __shared__ double ssum[256], ssum2[256];
    __shared__ float sct[FIL];
    int tid = threadIdx.x;  // 256
    int f = tid & 63, seg = tid >> 6;
    double s = 0.0, s2 = 0.0;
    for (int blk = seg; blk < NTILE1 * BATCH; blk += 4) {
        s  += (double)g_part[(blk * FIL + f) * 2 + 0];
        s2 += (double)g_part[(blk * FIL + f) * 2 + 1];
    }
    ssum[tid] = s; ssum2[tid] = s2;
    __syncthreads();
    if (seg == 0) {
        for (int k = 1; k < 4; ++k) { s += ssum[f + 64 * k]; s2 += ssum2[f + 64 * k]; }
        double N = (double)BATCH * (double)T2;
        double mud = s / N;
        float mu = (float)mud;
        float var = (float)(s2 / N - mud * mud);
        float scale = gamma[f] * rsqrtf(var + BN_EPSF);
        float shift = beta[f] - mu * scale;
        float wsum = 0.f;
        for (int k = 0; k < WIN; ++k) {
            float wv = w2[f * WIN + k];
            g_we2[f * WIN + k] = wv * scale;
            wsum += wv;
        }
        sct[f] = shift * wsum;
    }
    __syncthreads();
    if (tid == 0) {
        float c = b2[0];
        for (int i = 0; i < FIL; ++i) c += sct[i];
        g_cterm = c;
    }
}

// ---------------- K3: conv2 + relu + sigmoid + bucket index (R11 form) -------
extern "C" __global__ void k3_conv2_idx() {
    extern __shared__ float sm3[];
    float* sh   = sm3;                      // (TILE3+4)*SH3
    float* swe2 = sh + (TILE3 + 4) * SH3;   // WIN*FIL  layout [k][f]
    __shared__ float sct;
    int tile = blockIdx.x, b = blockIdx.y;
    int t0 = tile * TILE3;
    int tid = threadIdx.x;  // 128

    for (int o = tid; o < (TILE3 + 4) * FIL; o += 128) {
        int tl = o >> 6, ff = o & 63;
        int t = t0 + tl;
        sh[tl * SH3 + ff] = (t < T2) ? g_h2[((size_t)b * T2 + t) * FIL + ff] : 0.f;
    }
    for (int o = tid; o < FIL * WIN; o += 128) {
        int ff = o & 63, k = o >> 6;     // o = k*64+ff
        swe2[k * FIL + ff] = g_we2[ff * WIN + k];
    }
    if (tid == 0) sct = g_cterm;
    __syncthreads();

    int l = t0 + tid;
    if (l < LL) {
        float z = sct;
        const float* hb = sh + tid * SH3;
#pragma unroll 4
        for (int f = 0; f < FIL; f += 4) {
            float4 h0 = *(const float4*)(hb + f);
            float4 h1 = *(const float4*)(hb + SH3 + f);
            float4 h2 = *(const float4*)(hb + 2 * SH3 + f);
            float4 h3 = *(const float4*)(hb + 3 * SH3 + f);
            float4 h4 = *(const float4*)(hb + 4 * SH3 + f);
            float4 w0 = *(const float4*)(swe2 + f);
            float4 w1 = *(const float4*)(swe2 + FIL + f);
            float4 w2 = *(const float4*)(swe2 + 2 * FIL + f);
            float4 w3 = *(const float4*)(swe2 + 3 * FIL + f);
            float4 w4 = *(const float4*)(swe2 + 4 * FIL + f);
            z += w0.x * h0.x + w1.x * h1.x + w2.x * h2.x + w3.x * h3.x + w4.x * h4.x;
            z += w0.y * h0.y + w1.y * h1.y + w2.y * h2.y + w3.y * h3.y + w4.y * h4.y;
            z += w0.z * h0.z + w1.z * h1.z + w2.z * h2.z + w3.z * h3.z + w4.z * h4.z;
            z += w0.w * h0.w + w1.w * h1.w + w2.w * h2.w + w3.w * h3.w + w4.w * h4.w;
        }
        z = fmaxf(z, 0.f);
        float c = 1.f / (1.f + expf(-z));
        int iv = (int)ceilf(c * 256.f) - 1;
        iv = max(0, min(255, iv));
        g_idx[b * LL + l] = iv;
    }
}

// ---------------- K4: run-length atomic scatter, 8-way l-split ---------------
// EXACT R7/R11 algorithm (validated at 330/320us), but 512 threads =
// 8 l-segments x 64 a: walk length 509 -> ~255. Same total ATOMS, same smem,
// 64 CTAs = single wave so the extra warps are free latency hiding.
extern "C" __global__ void k4_scatter() {
    extern __shared__ float sm4[];
    float* sG   = sm4;                         // DA*257
    int* shist  = (int*)(sG + DA * 257);       // 256
    int* sscan  = shist + 256;                 // 256
    int* spos   = sscan + 256;                 // 256
    int b = blockIdx.x;
    int tid = threadIdx.x;  // 512
    for (int o = tid; o < DA * 257; o += 512) sG[o] = 0.f;
    if (tid < 256) shist[tid] = 0;
    __syncthreads();

    int a = tid & 63, g = tid >> 6;            // g in 0..7
    int l0 = (g * LL) / 8, l1 = ((g + 1) * LL) / 8;
    int jprev = -1, cacc = 0;
    float wacc = 0.f;
    for (int l = l0; l < l1; ++l) {
        int j = g_idx[b * LL + l];
        float wv = g_W1T[l * DA + a];
        if (j != jprev) {
            if (jprev >= 0) {
                atomicAdd(&sG[a * 257 + jprev], wacc);
                if (a == 0) atomicAdd(&shist[jprev], cacc);
            }
            jprev = j; wacc = wv; cacc = 1;
        } else { wacc += wv; ++cacc; }
    }
    if (jprev >= 0) {
        atomicAdd(&sG[a * 257 + jprev], wacc);
        if (a == 0) atomicAdd(&shist[jprev], cacc);
    }
    __syncthreads();

    // compact: prefix-sum of occupancy flags (tid<256 active, all at barriers)
    int cflag = 0;
    if (tid < 256) {
        cflag = (shist[tid] > 0) ? 1 : 0;
        sscan[tid] = cflag;
    }
    __syncthreads();
    for (int off = 1; off < 256; off <<= 1) {
        int add = (tid < 256 && tid >= off) ? sscan[tid - off] : 0;
        __syncthreads();
        if (tid < 256) sscan[tid] += add;
        __syncthreads();
    }
    if (tid < 256) {
        int pos = sscan[tid] - cflag;
        spos[tid] = pos;
        if (cflag) g_jlist[b * DD + pos] = tid;
        if (tid == 255) g_nact[b] = sscan[255];
        g_cnt[b * DD + tid] = shist[tid];
    }
    __syncthreads();

    for (int o = tid; o < DD * DA; o += 512) {
        int j = o >> 6, aa = o & 63;
        if (shist[j] > 0)
            g_Gc[((size_t)b * DD + spos[j]) * DA + aa] = sG[aa * 257 + j];
    }
}

// ---------------- K5: t = tanh(Gc @ emb_active); A = W2^T t ----------------
extern "C" __global__ void k5_gemm(const float* __restrict__ emb,
                                   const float* __restrict__ W2) {
    extern __shared__ float sm5[];
    float* sGT = sm5;                   // DD*JP (only nact rows used)
    float* sA  = sGT + DD * JP;         // 128
    float* sW2 = sA + 128;              // 64
    int*   sjl = (int*)(sW2 + DA);      // 256
    int b = blockIdx.x, half = blockIdx.y;
    int tid = threadIdx.x;  // 128

    int nact = g_nact[b];
    for (int o = tid; o < nact * DA; o += 128) {
        int jj = o >> 6, a = o & 63;
        sGT[jj * JP + a] = g_Gc[((size_t)b * DD + jj) * DA + a];
    }
    for (int o = tid; o < DD; o += 128) sjl[o] = g_jlist[b * DD + o];
    sA[tid] = 0.f;
    if (tid < DA) sW2[tid] = W2[tid];
    __syncthreads();

    int ta = tid >> 4, td = tid & 15;   // 8 x 16
    int a0 = ta * 8;
    int d0 = half * 128 + td * 8;
    float acc[8][8];
#pragma unroll
    for (int r = 0; r < 8; ++r)
#pragma unroll
        for (int s = 0; s < 8; ++s) acc[r][s] = 0.f;

    for (int jj = 0; jj < nact; ++jj) {
        const float* er = emb + (size_t)sjl[jj] * DD + d0;
        float4 ga = *(const float4*)&sGT[jj * JP + a0];
        float4 gb = *(const float4*)&sGT[jj * JP + a0 + 4];
        float4 e0 = __ldg((const float4*)er);
        float4 e1 = __ldg((const float4*)(er + 4));
        float gv[8] = {ga.x, ga.y, ga.z, ga.w, gb.x, gb.y, gb.z, gb.w};
        float ev[8] = {e0.x, e0.y, e0.z, e0.w, e1.x, e1.y, e1.z, e1.w};
#pragma unroll
        for (int r = 0; r < 8; ++r)
#pragma unroll
            for (int s = 0; s < 8; ++s)
                acc[r][s] = fmaf(gv[r], ev[s], acc[r][s]);
    }

    float pA[8];
#pragma unroll
    for (int s = 0; s < 8; ++s) pA[s] = 0.f;
#pragma unroll
    for (int r = 0; r < 8; ++r) {
        float wv = sW2[a0 + r];
#pragma unroll
        for (int s = 0; s < 8; ++s)
            pA[s] = fmaf(wv, tanhf(acc[r][s]), pA[s]);
    }
#pragma unroll
    for (int s = 0; s < 8; ++s)
        atomicAdd(&sA[td * 8 + s], pA[s]);
    __syncthreads();
    g_A[b * DD + half * 128 + tid] = sA[tid];
}

// ---------------- K6: bucket softmax + att gather + scores ----------------
extern "C" __global__ void k6_final(const float* __restrict__ emb,
                                    const float* __restrict__ lin_w,
                                    const float* __restrict__ lin_b,
                                    float* __restrict__ out) {
    __shared__ float sA[DD];
    __shared__ float sE[DD];
    __shared__ float red[256];
    int b = blockIdx.x;
    int tid = threadIdx.x;  // 256
    sA[tid] = g_A[b * DD + tid];
    __syncthreads();

    int j = tid;
    float P = 0.f;
    const float4* er = (const float4*)(emb + (size_t)j * DD);
#pragma unroll 8
    for (int d4 = 0; d4 < DD / 4; ++d4) {
        float4 e = __ldg(er + d4);
        P += e.x * sA[d4 * 4 + 0] + e.y * sA[d4 * 4 + 1]
           + e.z * sA[d4 * 4 + 2] + e.w * sA[d4 * 4 + 3];
    }
    int cj = g_cnt[b * DD + j];
    red[tid] = (cj > 0) ? P : -3.0e38f;
    __syncthreads();
    for (int st = 128; st > 0; st >>= 1) {
        if (tid < st) red[tid] = fmaxf(red[tid], red[tid + st]);
        __syncthreads();
    }
    float m = red[0];
    __syncthreads();
    float ex = (cj > 0) ? expf(P - m) : 0.f;
    red[tid] = (float)cj * ex;
    __syncthreads();
    for (int st = 128; st > 0; st >>= 1) {
        if (tid < st) red[tid] += red[tid + st];
        __syncthreads();
    }
    float Z = red[0];
    sE[j] = ex / Z;
    __syncthreads();

    for (int l = tid; l < LL; l += 256)
        out[b * LL + l] = sE[g_idx[b * LL + l]];

    if (tid < SEC) {
        float s = lin_b[tid];
        const float* wr = lin_w + tid * DD;
        for (int d = 0; d < DD; ++d) s += wr[d] * sA[d];
        out[BATCH * LL + b * SEC + tid] = s;
    }
}

// ---------------- launch ----------------
extern "C" void kernel_launch(void* const* d_in, const int* in_sizes, int n_in,
                              void* d_out, int out_size) {
    const float* x     = (const float*)d_in[0];
    const float* c1w   = (const float*)d_in[1];
    const float* c1b   = (const float*)d_in[2];
    const float* gamma = (const float*)d_in[3];
    const float* beta  = (const float*)d_in[4];
    const float* c2w   = (const float*)d_in[5];
    const float* c2b   = (const float*)d_in[6];
    const float* emb   = (const float*)d_in[7];
    const float* W1    = (const float*)d_in[8];
    const float* W2    = (const float*)d_in[9];
    const float* lw    = (const float*)d_in[10];
    const float* lb    = (const float*)d_in[11];
    float* out = (float*)d_out;

    size_t sm1 = (size_t)(CIN * INT_ + 8 * 32 * 2) * sizeof(float);
    size_t sm3 = (size_t)((TILE3 + 4) * SH3 + WIN * FIL) * sizeof(float);
    size_t sm4 = (size_t)DA * 257 * sizeof(float) + 3 * 256 * sizeof(int);
    size_t sm5 = (size_t)(DD * JP + 128 + DA) * sizeof(float) + DD * sizeof(int);
    cudaFuncSetAttribute(k1_conv_pool, cudaFuncAttributeMaxDynamicSharedMemorySize, (int)sm1);
    cudaFuncSetAttribute(k3_conv2_idx, cudaFuncAttributeMaxDynamicSharedMemorySize, (int)sm3);
    cudaFuncSetAttribute(k4_scatter,   cudaFuncAttributeMaxDynamicSharedMemorySize, (int)sm4);
    cudaFuncSetAttribute(k5_gemm,      cudaFuncAttributeMaxDynamicSharedMemorySize, (int)sm5);

    int nh = (LL * DA) / 2;
    k0a_prep<<<(nh + 255) / 256, 256>>>(W1);
    k0b_prep<<<(nh + 255) / 256, 256>>>(W1);
    k0c_prep<<<(CIN * WIN * FIL + 255) / 256, 256>>>(c1w);
    k1_conv_pool<<<dim3(NTILE1, BATCH), 256, sm1>>>(x, c1b);   // 4th launch -> ncu
    k2_stats<<<1, 256>>>(c2w, c2b, gamma, beta);
    k3_conv2_idx<<<dim3(NTILE3, BATCH), 128, sm3>>>();
    k4_scatter<<<BATCH, 512, sm4>>>();
    k5_gemm<<<dim3(BATCH, 2), 128, sm5>>>(emb, W2);
    k6_final<<<BATCH, 256>>>(emb, lw, lb, out);
}

// round 16
// speedup vs baseline: 1.8956x; 1.0709x over previous
#include <cuda_runtime.h>
#include <math.h>

#define BATCH 64
#define CIN 32
#define T_IN 2048
#define FIL 64
#define WIN 5
#define T1 2044
#define T2 2040
#define LL 2036
#define DA 64
#define DD 256
#define SEC 11
#define BN_EPSF 1e-5f

#define TILE 128        // pooled outputs per k1 block
#define INT_ 136        // input positions per k1 tile
#define NTILE1 16       // k1 tiles over T2
#define TILE3 128       // l positions per k3 block
#define NTILE3 16       // k3 tiles over LL
#define SH3 68          // float4-alignable [t][f] stride in k3
#define JP 68           // padded a-stride for sGT in k5
#define K4T 1024        // k4 threads (16-way l-split x 64 a)

// ---------------- scratch (device globals) ----------------
__device__ float g_h2[BATCH * T2 * FIL];            // pooled conv1 out, [b][t][f]
__device__ float g_part[NTILE1 * BATCH * FIL * 2];  // per-block BN partials
__device__ float g_we2[FIL * WIN];
__device__ float g_cterm;
__device__ int   g_idx[BATCH * LL];
__device__ float g_W1T[LL * DA];                    // W1 transposed [l][a]
__device__ float g_w1T[CIN * WIN * FIL];            // conv1 w transposed [c][k][f]
__device__ float g_Gc[BATCH * DD * DA];             // compact G [b][jj][a]
__device__ int   g_jlist[BATCH * DD];
__device__ int   g_nact[BATCH];
__device__ int   g_cnt[BATCH * DD];
__device__ float g_A[BATCH * DD];

// ---------------- K0 split into 3 launches so k1 is the 4th launch ----------
extern "C" __global__ void k0a_prep(const float* __restrict__ W1) {
    int t = blockIdx.x * 256 + threadIdx.x;          // first half of W1T
    if (t < (LL * DA) / 2) {
        int l = t >> 6, a = t & 63;
        g_W1T[t] = W1[a * LL + l];
    }
}
extern "C" __global__ void k0b_prep(const float* __restrict__ W1) {
    int t = (LL * DA) / 2 + blockIdx.x * 256 + threadIdx.x;  // second half
    if (t < LL * DA) {
        int l = t >> 6, a = t & 63;
        g_W1T[t] = W1[a * LL + l];
    }
}
extern "C" __global__ void k0c_prep(const float* __restrict__ w1) {
    int u = blockIdx.x * 256 + threadIdx.x;
    if (u < CIN * WIN * FIL) {
        int f = u & 63, ck = u >> 6;          // ck = c*5+k
        g_w1T[u] = w1[f * (CIN * WIN) + ck];
    }
}

// ---------------- K1: conv1 + maxpool5 + BN partials -------------------------
// Arithmetic expression UNCHANGED (validated). Change: x shared loads
// vectorized to LDS.128 (xr is 16B-aligned: c*136 + q*32; i+4 multiples of 4).
// 10 LDS.128 vs 40 LDS.32 per channel -> ~13% fewer issue slots on an
// issue-bound kernel (R15 ncu: issue=67.7%, fma=49.7%).
extern "C" __global__ void __launch_bounds__(256, 3)
k1_conv_pool(const float* __restrict__ x, const float* __restrict__ b1) {
    extern __shared__ float sm[];
    float* sx  = sm;                    // CIN*INT_  (4352)
    float* sst = sx + CIN * INT_;       // 8*32*2    (512)

    int tile = blockIdx.x, b = blockIdx.y;
    int t0 = tile * TILE;
    int tid = threadIdx.x;
    int w = tid >> 5, lane = tid & 31;
    int q = w >> 1, fhi = w & 1;
    int f = fhi * 32 + lane;
    int npool = min(TILE, T2 - t0);

    for (int i = tid; i < CIN * INT_; i += 256) {
        int c = i / INT_, p = i - c * INT_;
        int g = t0 + p;
        sx[i] = (g < T_IN) ? x[(b * CIN + c) * T_IN + g] : 0.f;
    }
    __syncthreads();

    float acc[36];
    float bias = __ldg(&b1[f]);
#pragma unroll
    for (int i = 0; i < 36; ++i) acc[i] = bias;

    int base = q * 32;
    for (int c = 0; c < CIN; ++c) {
        const float* wr = g_w1T + c * WIN * FIL + f;
        float w0 = __ldg(wr), wa = __ldg(wr + FIL), wb = __ldg(wr + 2 * FIL),
              wc = __ldg(wr + 3 * FIL), wd = __ldg(wr + 4 * FIL);
        const float* xr = sx + c * INT_ + base;     // 16B-aligned
        float4 xv0 = *(const float4*)xr;
        float x0 = xv0.x, x1 = xv0.y, x2 = xv0.z, x3 = xv0.w;
#pragma unroll
        for (int ii = 0; ii < 36; ii += 4) {
            float4 xv = *(const float4*)(xr + ii + 4);   // aligned LDS.128
            {
                float x4 = xv.x;
                acc[ii + 0] += w0 * x0 + wa * x1 + wb * x2 + wc * x3 + wd * x4;
                x0 = x1; x1 = x2; x2 = x3; x3 = x4;
            }
            {
                float x4 = xv.y;
                acc[ii + 1] += w0 * x0 + wa * x1 + wb * x2 + wc * x3 + wd * x4;
                x0 = x1; x1 = x2; x2 = x3; x3 = x4;
            }
            {
                float x4 = xv.z;
                acc[ii + 2] += w0 * x0 + wa * x1 + wb * x2 + wc * x3 + wd * x4;
                x0 = x1; x1 = x2; x2 = x3; x3 = x4;
            }
            {
                float x4 = xv.w;
                acc[ii + 3] += w0 * x0 + wa * x1 + wb * x2 + wc * x3 + wd * x4;
                x0 = x1; x1 = x2; x2 = x3; x3 = x4;
            }
        }
    }

    float ls = 0.f, ls2 = 0.f;
    float* h2row = g_h2 + ((size_t)b * T2 + t0) * FIL + f;
#pragma unroll
    for (int i = 0; i < 32; ++i) {
        float m = acc[i];
        m = fmaxf(m, acc[i + 1]); m = fmaxf(m, acc[i + 2]);
        m = fmaxf(m, acc[i + 3]); m = fmaxf(m, acc[i + 4]);
        int p = base + i;
        if (p < npool) {
            h2row[(size_t)p * FIL] = m;
            ls += m; ls2 += m * m;
        }
    }
    sst[(w * 32 + lane) * 2 + 0] = ls;
    sst[(w * 32 + lane) * 2 + 1] = ls2;
    __syncthreads();

    if (tid < FIL) {
        int fh = tid >> 5, ln = tid & 31;
        float s = 0.f, s2 = 0.f;
        for (int qq = 0; qq < 4; ++qq) {
            int ww = qq * 2 + fh;
            s  += sst[(ww * 32 + ln) * 2 + 0];
            s2 += sst[(ww * 32 + ln) * 2 + 1];
        }
        int blk = b * NTILE1 + tile;
        g_part[(blk * FIL + tid) * 2 + 0] = s;
        g_part[(blk * FIL + tid) * 2 + 1] = s2;
    }
}

// ---------------- K2: reduce BN stats (UNCHANGED / validated) ----------------
extern "C" __global__ void k2_stats(const float* __restrict__ w2,
                                    const float* __restrict__ b2,
                                    const float* __restrict__ gamma,
                                    const float* __restrict__ beta) {
    __shared__ double ssum[256], ssum2[256];
    __shared__ float sct[FIL];
    int tid = threadIdx.x;  // 256
    int f = tid & 63, seg = tid >> 6;
    double s = 0.0, s2 = 0.0;
    for (int blk = seg; blk < NTILE1 * BATCH; blk += 4) {
        s  += (double)g_part[(blk * FIL + f) * 2 + 0];
        s2 += (double)g_part[(blk * FIL + f) * 2 + 1];
    }
    ssum[tid] = s; ssum2[tid] = s2;
    __syncthreads();
    if (seg == 0) {
        for (int k = 1; k < 4; ++k) { s += ssum[f + 64 * k]; s2 += ssum2[f + 64 * k]; }
        double N = (double)BATCH * (double)T2;
        double mud = s / N;
        float mu = (float)mud;
        float var = (float)(s2 / N - mud * mud);
        float scale = gamma[f] * rsqrtf(var + BN_EPSF);
        float shift = beta[f] - mu * scale;
        float wsum = 0.f;
        for (int k = 0; k < WIN; ++k) {
            float wv = w2[f * WIN + k];
            g_we2[f * WIN + k] = wv * scale;
            wsum += wv;
        }
        sct[f] = shift * wsum;
    }
    __syncthreads();
    if (tid == 0) {
        float c = b2[0];
        for (int i = 0; i < FIL; ++i) c += sct[i];
        g_cterm = c;
    }
}

// ---------------- K3: conv2 + relu + sigmoid + bucket index (R11 form) -------
extern "C" __global__ void k3_conv2_idx() {
    extern __shared__ float sm3[];
    float* sh   = sm3;                      // (TILE3+4)*SH3
    float* swe2 = sh + (TILE3 + 4) * SH3;   // WIN*FIL  layout [k][f]
    __shared__ float sct;
    int tile = blockIdx.x, b = blockIdx.y;
    int t0 = tile * TILE3;
    int tid = threadIdx.x;  // 128

    for (int o = tid; o < (TILE3 + 4) * FIL; o += 128) {
        int tl = o >> 6, ff = o & 63;
        int t = t0 + tl;
        sh[tl * SH3 + ff] = (t < T2) ? g_h2[((size_t)b * T2 + t) * FIL + ff] : 0.f;
    }
    for (int o = tid; o < FIL * WIN; o += 128) {
        int ff = o & 63, k = o >> 6;     // o = k*64+ff
        swe2[k * FIL + ff] = g_we2[ff * WIN + k];
    }
    if (tid == 0) sct = g_cterm;
    __syncthreads();

    int l = t0 + tid;
    if (l < LL) {
        float z = sct;
        const float* hb = sh + tid * SH3;
#pragma unroll 4
        for (int f = 0; f < FIL; f += 4) {
            float4 h0 = *(const float4*)(hb + f);
            float4 h1 = *(const float4*)(hb + SH3 + f);
            float4 h2 = *(const float4*)(hb + 2 * SH3 + f);
            float4 h3 = *(const float4*)(hb + 3 * SH3 + f);
            float4 h4 = *(const float4*)(hb + 4 * SH3 + f);
            float4 w0 = *(const float4*)(swe2 + f);
            float4 w1 = *(const float4*)(swe2 + FIL + f);
            float4 w2 = *(const float4*)(swe2 + 2 * FIL + f);
            float4 w3 = *(const float4*)(swe2 + 3 * FIL + f);
            float4 w4 = *(const float4*)(swe2 + 4 * FIL + f);
            z += w0.x * h0.x + w1.x * h1.x + w2.x * h2.x + w3.x * h3.x + w4.x * h4.x;
            z += w0.y * h0.y + w1.y * h1.y + w2.y * h2.y + w3.y * h3.y + w4.y * h4.y;
            z += w0.z * h0.z + w1.z * h1.z + w2.z * h2.z + w3.z * h3.z + w4.z * h4.z;
            z += w0.w * h0.w + w1.w * h1.w + w2.w * h2.w + w3.w * h3.w + w4.w * h4.w;
        }
        z = fmaxf(z, 0.f);
        float c = 1.f / (1.f + expf(-z));
        int iv = (int)ceilf(c * 256.f) - 1;
        iv = max(0, min(255, iv));
        g_idx[b * LL + l] = iv;
    }
}

// ---------------- K4: run-length atomic scatter, 16-way l-split --------------
// R7/R11 algorithm; 1024 threads = 16 l-segments x 64 a (walk ~127). Same
// total ATOMS, same smem; 64 CTAs = single wave (R15 validated this scaling
// direction at 8-way: -41us).
extern "C" __global__ void k4_scatter() {
    extern __shared__ float sm4[];
    float* sG   = sm4;                         // DA*257
    int* shist  = (int*)(sG + DA * 257);       // 256
    int* sscan  = shist + 256;                 // 256
    int* spos   = sscan + 256;                 // 256
    int b = blockIdx.x;
    int tid = threadIdx.x;  // 1024
    for (int o = tid; o < DA * 257; o += K4T) sG[o] = 0.f;
    if (tid < 256) shist[tid] = 0;
    __syncthreads();

    int a = tid & 63, g = tid >> 6;            // g in 0..15
    int l0 = (g * LL) / 16, l1 = ((g + 1) * LL) / 16;
    int jprev = -1, cacc = 0;
    float wacc = 0.f;
    for (int l = l0; l < l1; ++l) {
        int j = g_idx[b * LL + l];
        float wv = g_W1T[l * DA + a];
        if (j != jprev) {
            if (jprev >= 0) {
                atomicAdd(&sG[a * 257 + jprev], wacc);
                if (a == 0) atomicAdd(&shist[jprev], cacc);
            }
            jprev = j; wacc = wv; cacc = 1;
        } else { wacc += wv; ++cacc; }
    }
    if (jprev >= 0) {
        atomicAdd(&sG[a * 257 + jprev], wacc);
        if (a == 0) atomicAdd(&shist[jprev], cacc);
    }
    __syncthreads();

    // compact: prefix-sum of occupancy flags (tid<256 active, all at barriers)
    int cflag = 0;
    if (tid < 256) {
        cflag = (shist[tid] > 0) ? 1 : 0;
        sscan[tid] = cflag;
    }
    __syncthreads();
    for (int off = 1; off < 256; off <<= 1) {
        int add = (tid < 256 && tid >= off) ? sscan[tid - off] : 0;
        __syncthreads();
        if (tid < 256) sscan[tid] += add;
        __syncthreads();
    }
    if (tid < 256) {
        int pos = sscan[tid] - cflag;
        spos[tid] = pos;
        if (cflag) g_jlist[b * DD + pos] = tid;
        if (tid == 255) g_nact[b] = sscan[255];
        g_cnt[b * DD + tid] = shist[tid];
    }
    __syncthreads();

    for (int o = tid; o < DD * DA; o += K4T) {
        int j = o >> 6, aa = o & 63;
        if (shist[j] > 0)
            g_Gc[((size_t)b * DD + spos[j]) * DA + aa] = sG[aa * 257 + j];
    }
}

// ---------------- K5: t = tanh(Gc @ emb_active); A = W2^T t ----------------
extern "C" __global__ void k5_gemm(const float* __restrict__ emb,
                                   const float* __restrict__ W2) {
    extern __shared__ float sm5[];
    float* sGT = sm5;                   // DD*JP (only nact rows used)
    float* sA  = sGT + DD * JP;         // 128
    float* sW2 = sA + 128;              // 64
    int*   sjl = (int*)(sW2 + DA);      // 256
    int b = blockIdx.x, half = blockIdx.y;
    int tid = threadIdx.x;  // 128

    int nact = g_nact[b];
    for (int o = tid; o < nact * DA; o += 128) {
        int jj = o >> 6, a = o & 63;
        sGT[jj * JP + a] = g_Gc[((size_t)b * DD + jj) * DA + a];
    }
    for (int o = tid; o < DD; o += 128) sjl[o] = g_jlist[b * DD + o];
    sA[tid] = 0.f;
    if (tid < DA) sW2[tid] = W2[tid];
    __syncthreads();

    int ta = tid >> 4, td = tid & 15;   // 8 x 16
    int a0 = ta * 8;
    int d0 = half * 128 + td * 8;
    float acc[8][8];
#pragma unroll
    for (int r = 0; r < 8; ++r)
#pragma unroll
        for (int s = 0; s < 8; ++s) acc[r][s] = 0.f;

    for (int jj = 0; jj < nact; ++jj) {
        const float* er = emb + (size_t)sjl[jj] * DD + d0;
        float4 ga = *(const float4*)&sGT[jj * JP + a0];
        float4 gb = *(const float4*)&sGT[jj * JP + a0 + 4];
        float4 e0 = __ldg((const float4*)er);
        float4 e1 = __ldg((const float4*)(er + 4));
        float gv[8] = {ga.x, ga.y, ga.z, ga.w, gb.x, gb.y, gb.z, gb.w};
        float ev[8] = {e0.x, e0.y, e0.z, e0.w, e1.x, e1.y, e1.z, e1.w};
#pragma unroll
        for (int r = 0; r < 8; ++r)
#pragma unroll
            for (int s = 0; s < 8; ++s)
                acc[r][s] = fmaf(gv[r], ev[s], acc[r][s]);
    }

    float pA[8];
#pragma unroll
    for (int s = 0; s < 8; ++s) pA[s] = 0.f;
#pragma unroll
    for (int r = 0; r < 8; ++r) {
        float wv = sW2[a0 + r];
#pragma unroll
        for (int s = 0; s < 8; ++s)
            pA[s] = fmaf(wv, tanhf(acc[r][s]), pA[s]);
    }
#pragma unroll
    for (int s = 0; s < 8; ++s)
        atomicAdd(&sA[td * 8 + s], pA[s]);
    __syncthreads();
    g_A[b * DD + half * 128 + tid] = sA[tid];
}

// ---------------- K6: bucket softmax + att gather + scores ----------------
extern "C" __global__ void k6_final(const float* __restrict__ emb,
                                    const float* __restrict__ lin_w,
                                    const float* __restrict__ lin_b,
                                    float* __restrict__ out) {
    __shared__ float sA[DD];
    __shared__ float sE[DD];
    __shared__ float red[256];
    int b = blockIdx.x;
    int tid = threadIdx.x;  // 256
    sA[tid] = g_A[b * DD + tid];
    __syncthreads();

    int j = tid;
    float P = 0.f;
    const float4* er = (const float4*)(emb + (size_t)j * DD);
#pragma unroll 8
    for (int d4 = 0; d4 < DD / 4; ++d4) {
        float4 e = __ldg(er + d4);
        P += e.x * sA[d4 * 4 + 0] + e.y * sA[d4 * 4 + 1]
           + e.z * sA[d4 * 4 + 2] + e.w * sA[d4 * 4 + 3];
    }
    int cj = g_cnt[b * DD + j];
    red[tid] = (cj > 0) ? P : -3.0e38f;
    __syncthreads();
    for (int st = 128; st > 0; st >>= 1) {
        if (tid < st) red[tid] = fmaxf(red[tid], red[tid + st]);
        __syncthreads();
    }
    float m = red[0];
    __syncthreads();
    float ex = (cj > 0) ? expf(P - m) : 0.f;
    red[tid] = (float)cj * ex;
    __syncthreads();
    for (int st = 128; st > 0; st >>= 1) {
        if (tid < st) red[tid] += red[tid + st];
        __syncthreads();
    }
    float Z = red[0];
    sE[j] = ex / Z;
    __syncthreads();

    for (int l = tid; l < LL; l += 256)
        out[b * LL + l] = sE[g_idx[b * LL + l]];

    if (tid < SEC) {
        float s = lin_b[tid];
        const float* wr = lin_w + tid * DD;
        for (int d = 0; d < DD; ++d) s += wr[d] * sA[d];
        out[BATCH * LL + b * SEC + tid] = s;
    }
}

// ---------------- launch ----------------
extern "C" void kernel_launch(void* const* d_in, const int* in_sizes, int n_in,
                              void* d_out, int out_size) {
    const float* x     = (const float*)d_in[0];
    const float* c1w   = (const float*)d_in[1];
    const float* c1b   = (const float*)d_in[2];
    const float* gamma = (const float*)d_in[3];
    const float* beta  = (const float*)d_in[4];
    const float* c2w   = (const float*)d_in[5];
    const float* c2b   = (const float*)d_in[6];
    const float* emb   = (const float*)d_in[7];
    const float* W1    = (const float*)d_in[8];
    const float* W2    = (const float*)d_in[9];
    const float* lw    = (const float*)d_in[10];
    const float* lb    = (const float*)d_in[11];
    float* out = (float*)d_out;

    size_t sm1 = (size_t)(CIN * INT_ + 8 * 32 * 2) * sizeof(float);
    size_t sm3 = (size_t)((TILE3 + 4) * SH3 + WIN * FIL) * sizeof(float);
    size_t sm4 = (size_t)DA * 257 * sizeof(float) + 3 * 256 * sizeof(int);
    size_t sm5 = (size_t)(DD * JP + 128 + DA) * sizeof(float) + DD * sizeof(int);
    cudaFuncSetAttribute(k1_conv_pool, cudaFuncAttributeMaxDynamicSharedMemorySize, (int)sm1);
    cudaFuncSetAttribute(k3_conv2_idx, cudaFuncAttributeMaxDynamicSharedMemorySize, (int)sm3);
    cudaFuncSetAttribute(k4_scatter,   cudaFuncAttributeMaxDynamicSharedMemorySize, (int)sm4);
    cudaFuncSetAttribute(k5_gemm,      cudaFuncAttributeMaxDynamicSharedMemorySize, (int)sm5);

    int nh = (LL * DA) / 2;
    k0a_prep<<<(nh + 255) / 256, 256>>>(W1);
    k0b_prep<<<(nh + 255) / 256, 256>>>(W1);
    k0c_prep<<<(CIN * WIN * FIL + 255) / 256, 256>>>(c1w);
    k1_conv_pool<<<dim3(NTILE1, BATCH), 256, sm1>>>(x, c1b);   // 4th launch -> ncu
    k2_stats<<<1, 256>>>(c2w, c2b, gamma, beta);
    k3_conv2_idx<<<dim3(NTILE3, BATCH), 128, sm3>>>();
    k4_scatter<<<BATCH, K4T, sm4>>>();
    k5_gemm<<<dim3(BATCH, 2), 128, sm5>>>(emb, W2);
    k6_final<<<BATCH, 256>>>(emb, lw, lb, out);
}